// round 16
// baseline (speedup 1.0000x reference)
#include <cuda_runtime.h>
#include <cuda_fp16.h>
#include <math.h>
#include <stdint.h>

// Problem constants
#define B_SZ   2
#define S_LEN  2048
#define HID    2048
#define NH     16
#define NKV    4
#define DH     128
#define GROUPS (NH / NKV)
#define ROWS   (B_SZ * S_LEN)        // 4096
#define NQKV   (NH * DH + 2 * NKV * DH)   // 3072

// Scratch
__device__ __half   g_Qh[ROWS * NH * DH];
__device__ __half   g_Kh[ROWS * NKV * DH];
__device__ __half   g_Vt[B_SZ * NKV * DH * S_LEN];   // [b][kvh][d][s]
__device__ uint32_t g_xp4[(ROWS / 16) * (HID / 16) * 32 * 4];
__device__ uint32_t g_Op4[(ROWS / 16) * ((NH * DH) / 16) * 32 * 4];
__device__ uint32_t g_wqkv2[(NQKV / 8) * (HID / 16) * 32 * 2];       // Q|K|V B-frags
__device__ uint32_t g_wop2[(HID / 8) * ((NH * DH) / 16) * 32 * 2];

// ---------------------------------------------------------------------------
// Helpers
// ---------------------------------------------------------------------------
__device__ __forceinline__ void mma_f16(float* d, const uint32_t* a, const uint32_t* b) {
    asm volatile(
        "mma.sync.aligned.m16n8k16.row.col.f32.f16.f16.f32 "
        "{%0,%1,%2,%3}, {%4,%5,%6,%7}, {%8,%9}, {%0,%1,%2,%3};\n"
        : "+f"(d[0]), "+f"(d[1]), "+f"(d[2]), "+f"(d[3])
        : "r"(a[0]), "r"(a[1]), "r"(a[2]), "r"(a[3]),
          "r"(b[0]), "r"(b[1]));
}

__device__ __forceinline__ uint32_t packh2(float a, float b) {
    __half2 h = __floats2half2_rn(a, b);
    return *(uint32_t*)&h;
}

__device__ __forceinline__ uint32_t smem_u32(const void* p) {
    return (uint32_t)__cvta_generic_to_shared(p);
}

#define CP16(dst, src) asm volatile("cp.async.cg.shared.global [%0], [%1], 16;" :: "r"(dst), "l"(src))
#define CP_COMMIT()    asm volatile("cp.async.commit_group;")
#define CP_WAIT(n)     asm volatile("cp.async.wait_group %0;" :: "n"(n))

// ---------------------------------------------------------------------------
// Mega-prep: all 5 permutes in one launch.
// ---------------------------------------------------------------------------
#define NU_A   ((ROWS / 16) * (HID / 16) * 32)
#define NU_WQ  (((NH * DH) / 8) * (HID / 16) * 32)
#define NU_WKV (((NKV * DH) / 8) * (HID / 16) * 32)
#define NU_WO  ((HID / 8) * ((NH * DH) / 16) * 32)
#define NU_TOTAL (NU_A + NU_WQ + 2 * NU_WKV + NU_WO)

__device__ __forceinline__ void permA_unit(
    const float* __restrict__ in, uint32_t* __restrict__ out, int K, int id)
{
    int KT = K >> 4;
    int lane = id & 31;
    int kt   = (id >> 5) % KT;
    int mt   = (id >> 5) / KT;
    int r  = mt * 16 + (lane >> 2);
    int cb = kt * 16 + 2 * (lane & 3);
    const float* p0 = in + (size_t)r * K + cb;
    const float* p1 = p0 + (size_t)8 * K;
    uint4 v;
    v.x = packh2(p0[0], p0[1]);
    v.y = packh2(p1[0], p1[1]);
    v.z = packh2(p0[8], p0[9]);
    v.w = packh2(p1[8], p1[9]);
    ((uint4*)out)[id] = v;
}

__device__ __forceinline__ void permB_unit(
    const float* __restrict__ in, uint32_t* __restrict__ out, int K, int N, int id)
{
    int KT = K >> 4;
    int lane = id & 31;
    int kt   = (id >> 5) % KT;
    int nt   = (id >> 5) / KT;
    int n  = nt * 8 + (lane >> 2);
    int kb = kt * 16 + 2 * (lane & 3);
    uint2 v;
    v.x = packh2(in[(size_t)kb * N + n],       in[(size_t)(kb + 1) * N + n]);
    v.y = packh2(in[(size_t)(kb + 8) * N + n], in[(size_t)(kb + 9) * N + n]);
    ((uint2*)out)[id] = v;
}

__global__ __launch_bounds__(256) void prep_all(
    const float* __restrict__ x,  const float* __restrict__ wq,
    const float* __restrict__ wk, const float* __restrict__ wv,
    const float* __restrict__ wo,
    uint32_t* __restrict__ xp4, uint32_t* __restrict__ wqkv2,
    uint32_t* __restrict__ wop2)
{
    int id = blockIdx.x * 256 + threadIdx.x;
    if (id < NU_A) {
        permA_unit(x, xp4, HID, id);
    } else if (id < NU_A + NU_WQ) {
        permB_unit(wq, wqkv2, HID, NH * DH, id - NU_A);
    } else if (id < NU_A + NU_WQ + NU_WKV) {
        permB_unit(wk, wqkv2 + (size_t)NU_WQ * 2, HID, NKV * DH,
                   id - NU_A - NU_WQ);
    } else if (id < NU_A + NU_WQ + 2 * NU_WKV) {
        permB_unit(wv, wqkv2 + (size_t)(NU_WQ + NU_WKV) * 2, HID, NKV * DH,
                   id - NU_A - NU_WQ - NU_WKV);
    } else if (id < NU_TOTAL) {
        permB_unit(wo, wop2, NH * DH, HID, id - NU_A - NU_WQ - 2 * NU_WKV);
    }
}

// ---------------------------------------------------------------------------
// Shared GEMM config (128x256 tile, 8 warps, BK=64, 4 stages).
// ---------------------------------------------------------------------------
#define HSA 16384
#define HSB 32768
#define HSTG (HSA + HSB)
#define HNSTG 4
#define HSMEM (HNSTG * HSTG)      // 196,608

__global__ __launch_bounds__(256, 1) void gemm_qkv(
    const uint32_t* __restrict__ Ap, const uint32_t* __restrict__ Bp,
    __half* __restrict__ Qh, __half* __restrict__ Kh, __half* __restrict__ Vt)
{
    extern __shared__ __align__(16) char smem[];

    const int tid  = threadIdx.x;
    const int lane = tid & 31;
    const int w    = tid >> 5;
    const int wm   = (w >> 2) * 64;
    const int wn   = (w & 3) * 64;
    const int bm   = blockIdx.y * 128;
    const int bn   = blockIdx.x * 256;

    const int K    = HID;
    const int KT16 = K >> 4;
    const int NT   = K >> 6;
    const int mt0  = bm >> 4;
    const int nt0  = bn >> 3;

    auto fill = [&](int buf, int kt0) {
        char* sA = smem + buf * HSTG;
        char* sB = sA + HSA;
#pragma unroll
        for (int i = 0; i < 4; i++) {
            int id = i * 256 + tid;
            int mt_i = id >> 7, kt_i = (id >> 5) & 3, ln = id & 31;
            size_t g = (((size_t)(mt0 + mt_i) * KT16 + kt0 + kt_i) * 32 + ln);
            CP16(smem_u32(sA + id * 16), (const char*)Ap + g * 16);
        }
#pragma unroll
        for (int i = 0; i < 8; i++) {
            int id = i * 256 + tid;
            int nt_i = id >> 6, kt_i = (id >> 4) & 3, u = id & 15;
            size_t g = (((size_t)(nt0 + nt_i) * KT16 + kt0 + kt_i) * 32 + 2 * u);
            CP16(smem_u32(sB + id * 16), (const char*)Bp + g * 8);
        }
    };

    fill(0, 0); CP_COMMIT();
    fill(1, 4); CP_COMMIT();
    fill(2, 8); CP_COMMIT();

    float acc[4][8][4] = {};

    for (int t = 0; t < NT; t++) {
        CP_WAIT(2);
        __syncthreads();
        if (t + 3 < NT) fill((t + 3) % HNSTG, (t + 3) * 4);
        CP_COMMIT();

        const char* sA = smem + (t % HNSTG) * HSTG;
        const char* sB = sA + HSA;

#pragma unroll
        for (int kt = 0; kt < 4; kt++) {
            uint4 af[4];
            uint2 bf[8];
#pragma unroll
            for (int mi = 0; mi < 4; mi++) {
                int mt_t = (wm >> 4) + mi;
                af[mi] = *(const uint4*)(sA + (((mt_t * 4 + kt) * 32 + lane) << 4));
            }
#pragma unroll
            for (int ni = 0; ni < 8; ni++) {
                int nt_t = (wn >> 3) + ni;
                bf[ni] = *(const uint2*)(sB + (((nt_t * 4 + kt) * 32 + lane) << 3));
            }
#pragma unroll
            for (int mi = 0; mi < 4; mi++)
#pragma unroll
                for (int ni = 0; ni < 8; ni++)
                    mma_f16(acc[mi][ni], (const uint32_t*)&af[mi], (const uint32_t*)&bf[ni]);
        }
    }

    const int region = (bn < NH * DH) ? 0 : (bn < NH * DH + NKV * DH ? 1 : 2);

#pragma unroll
    for (int mi = 0; mi < 4; mi++) {
        int r0 = bm + wm + mi * 16 + (lane >> 2);
#pragma unroll
        for (int ni = 0; ni < 8; ni++) {
            int c = bn + wn + ni * 8 + 2 * (lane & 3);
            float v0 = acc[mi][ni][0], v1 = acc[mi][ni][1];
            float v2 = acc[mi][ni][2], v3 = acc[mi][ni][3];
            if (region == 0) {
                *(uint32_t*)(Qh + (size_t)r0 * (NH * DH) + c)       = packh2(v0, v1);
                *(uint32_t*)(Qh + (size_t)(r0 + 8) * (NH * DH) + c) = packh2(v2, v3);
            } else if (region == 1) {
                int ck = c - NH * DH;
                *(uint32_t*)(Kh + (size_t)r0 * (NKV * DH) + ck)       = packh2(v0, v1);
                *(uint32_t*)(Kh + (size_t)(r0 + 8) * (NKV * DH) + ck) = packh2(v2, v3);
            } else {
                int cc = c - (NH * DH + NKV * DH);
                int b0 = r0 >> 11, s0 = r0 & 2047;
                int kvh = cc >> 7;
                int d0 = cc & 127;
                size_t base0 = (((size_t)(b0 * NKV + kvh) * DH + d0) * S_LEN);
                size_t base1 = base0 + S_LEN;
                Vt[base0 + s0]     = __float2half(v0);
                Vt[base1 + s0]     = __float2half(v1);
                Vt[base0 + s0 + 8] = __float2half(v2);
                Vt[base1 + s0 + 8] = __float2half(v3);
            }
        }
    }
}

__global__ __launch_bounds__(256, 1) void gemm_o(
    const uint32_t* __restrict__ Ap, const uint32_t* __restrict__ Bp,
    float* __restrict__ C, int M, int N, int K)
{
    extern __shared__ __align__(16) char smem[];

    const int tid  = threadIdx.x;
    const int lane = tid & 31;
    const int w    = tid >> 5;
    const int wm   = (w >> 2) * 64;
    const int wn   = (w & 3) * 64;
    const int bm   = blockIdx.y * 128;
    const int bn   = blockIdx.x * 256;

    const int KT16 = K >> 4;
    const int NT   = K >> 6;
    const int mt0  = bm >> 4;
    const int nt0  = bn >> 3;

    auto fill = [&](int buf, int kt0) {
        char* sA = smem + buf * HSTG;
        char* sB = sA + HSA;
#pragma unroll
        for (int i = 0; i < 4; i++) {
            int id = i * 256 + tid;
            int mt_i = id >> 7, kt_i = (id >> 5) & 3, ln = id & 31;
            size_t g = (((size_t)(mt0 + mt_i) * KT16 + kt0 + kt_i) * 32 + ln);
            CP16(smem_u32(sA + id * 16), (const char*)Ap + g * 16);
        }
#pragma unroll
        for (int i = 0; i < 8; i++) {
            int id = i * 256 + tid;
            int nt_i = id >> 6, kt_i = (id >> 4) & 3, u = id & 15;
            size_t g = (((size_t)(nt0 + nt_i) * KT16 + kt0 + kt_i) * 32 + 2 * u);
            CP16(smem_u32(sB + id * 16), (const char*)Bp + g * 8);
        }
    };

    fill(0, 0); CP_COMMIT();
    fill(1, 4); CP_COMMIT();
    fill(2, 8); CP_COMMIT();

    float acc[4][8][4] = {};

    for (int t = 0; t < NT; t++) {
        CP_WAIT(2);
        __syncthreads();
        if (t + 3 < NT) fill((t + 3) % HNSTG, (t + 3) * 4);
        CP_COMMIT();

        const char* sA = smem + (t % HNSTG) * HSTG;
        const char* sB = sA + HSA;

#pragma unroll
        for (int kt = 0; kt < 4; kt++) {
            uint4 af[4];
            uint2 bf[8];
#pragma unroll
            for (int mi = 0; mi < 4; mi++) {
                int mt_t = (wm >> 4) + mi;
                af[mi] = *(const uint4*)(sA + (((mt_t * 4 + kt) * 32 + lane) << 4));
            }
#pragma unroll
            for (int ni = 0; ni < 8; ni++) {
                int nt_t = (wn >> 3) + ni;
                bf[ni] = *(const uint2*)(sB + (((nt_t * 4 + kt) * 32 + lane) << 3));
            }
#pragma unroll
            for (int mi = 0; mi < 4; mi++)
#pragma unroll
                for (int ni = 0; ni < 8; ni++)
                    mma_f16(acc[mi][ni], (const uint32_t*)&af[mi], (const uint32_t*)&bf[ni]);
        }
    }

#pragma unroll
    for (int mi = 0; mi < 4; mi++) {
        int r0 = bm + wm + mi * 16 + (lane >> 2);
#pragma unroll
        for (int ni = 0; ni < 8; ni++) {
            int c = bn + wn + ni * 8 + 2 * (lane & 3);
            *(float2*)(C + (size_t)r0 * N + c) =
                make_float2(acc[mi][ni][0], acc[mi][ni][1]);
            *(float2*)(C + (size_t)(r0 + 8) * N + c) =
                make_float2(acc[mi][ni][2], acc[mi][ni][3]);
        }
    }
}

// ---------------------------------------------------------------------------
// RoPE on half Q/K (fp32 math); Q additionally scaled by 1/sqrt(DH).
// ---------------------------------------------------------------------------
__global__ __launch_bounds__(256) void rope_h(
    __half* __restrict__ Q, __half* __restrict__ Kt,
    const float* __restrict__ freqs)
{
    const int QP = ROWS * NH * (DH / 2);
    const int KP = ROWS * NKV * (DH / 2);
    const float scale = 0.08838834764831845f;
    int idx = blockIdx.x * blockDim.x + threadIdx.x;
    if (idx < QP) {
        int i   = idx & 63;
        int h   = (idx >> 6) & (NH - 1);
        int row = idx >> 10;
        int s   = row & (S_LEN - 1);
        float c  = freqs[s * 128 + 2 * i];
        float sn = freqs[s * 128 + 2 * i + 1];
        __half2* p = (__half2*)(Q + (size_t)row * (NH * DH) + h * DH + 2 * i);
        float2 v = __half22float2(*p);
        *p = __floats2half2_rn((v.x * c - v.y * sn) * scale,
                               (v.x * sn + v.y * c) * scale);
    } else if (idx < QP + KP) {
        int j   = idx - QP;
        int i   = j & 63;
        int h   = (j >> 6) & (NKV - 1);
        int row = j >> 8;
        int s   = row & (S_LEN - 1);
        float c  = freqs[s * 128 + 2 * i];
        float sn = freqs[s * 128 + 2 * i + 1];
        __half2* p = (__half2*)(Kt + (size_t)row * (NKV * DH) + h * DH + 2 * i);
        float2 v = __half22float2(*p);
        *p = __floats2half2_rn(v.x * c - v.y * sn, v.x * sn + v.y * c);
    }
}

// ---------------------------------------------------------------------------
// FP16 flash attention (causal, GQA). AQ=64, AK=64, 128 threads (4 warps),
// 2 CTAs/SM (smem 87KB). KT = qt+1; diagonal at kt == qt.
// ---------------------------------------------------------------------------
#define AQ 64
#define AK 64
#define QSH 136
#define VSH 72
#define ATT_SMEM ((AQ * QSH + 2 * AK * QSH + 2 * DH * VSH) * 2)

__global__ __launch_bounds__(128) void attn_h(
    const __half* __restrict__ Q, const __half* __restrict__ K,
    const __half* __restrict__ Vt, uint32_t* __restrict__ Op4)
{
    extern __shared__ __align__(16) __half sh[];
    __half* Qs  = sh;                        // [64][136]
    __half* Ks  = Qs + AQ * QSH;             // 2 x [64][136]
    __half* Vts = Ks + 2 * AK * QSH;         // 2 x [128][72]

    const int qt  = gridDim.x - 1 - blockIdx.x;   // heavy blocks first
    const int bh  = blockIdx.y;
    const int b   = bh >> 4;
    const int h   = bh & 15;
    const int kvh = h >> 2;
    const int tid = threadIdx.x;
    const int lane = tid & 31;
    const int w    = tid >> 5;               // 0..3
    const int cq   = lane & 3;

    const size_t qbaseH = ((size_t)(b * S_LEN + qt * AQ)) * (NH * DH) + h * DH;
#pragma unroll
    for (int i = 0; i < 8; i++) {
        int t = i * 128 + tid;               // 1024 units of 16B
        int r = t >> 4, u = t & 15;
        CP16(smem_u32(Qs + r * QSH + u * 8), Q + qbaseH + (size_t)r * (NH * DH) + u * 8);
    }

    const size_t kbaseH  = ((size_t)(b * S_LEN)) * (NKV * DH) + kvh * DH;
    const size_t vtbaseH = ((size_t)(b * NKV + kvh)) * DH * S_LEN;

    auto issueKV = [&](int buf, int kt) {
        __half* ks = Ks + buf * AK * QSH;
        __half* vs = Vts + buf * DH * VSH;
#pragma unroll
        for (int i = 0; i < 8; i++) {        // K: 64 rows x 16 units
            int id = i * 128 + tid;
            int r = id >> 4, u = id & 15;
            CP16(smem_u32(ks + r * QSH + u * 8),
                 K + kbaseH + (size_t)(kt * AK + r) * (NKV * DH) + u * 8);
        }
#pragma unroll
        for (int i = 0; i < 8; i++) {        // Vt: 128 d x 8 units
            int id = i * 128 + tid;
            int d = id >> 3, u = id & 7;
            CP16(smem_u32(vs + d * VSH + u * 8),
                 Vt + vtbaseH + (size_t)d * S_LEN + kt * AK + u * 8);
        }
    };

    const int KT = qt + 1;
    issueKV(0, 0); CP_COMMIT();

    const int rA = w * 16 + (lane >> 2);     // 0..63
    const int q0 = qt * AQ + rA;
    const int q1 = q0 + 8;

    float m0 = -INFINITY, m1 = -INFINITY, l0 = 0.f, l1 = 0.f;
    float oacc[16][4] = {};

    for (int kt = 0; kt < KT; kt++) {
        __syncthreads();
        if (kt + 1 < KT) issueKV((kt + 1) & 1, kt + 1);
        CP_COMMIT();
        CP_WAIT(1);
        __syncthreads();

        const __half* ks = Ks + (kt & 1) * AK * QSH;
        const __half* vs = Vts + (kt & 1) * DH * VSH;

        // S = Q @ Ktile^T   (8 k16 steps x 8 key groups)
        float sacc[8][4] = {};
        const __half* q0p = Qs + rA * QSH;
        const __half* q1p = q0p + 8 * QSH;
#pragma unroll
        for (int kk = 0; kk < DH; kk += 16) {
            uint32_t a[4];
            a[0] = *(const uint32_t*)(q0p + kk + 2 * cq);
            a[1] = *(const uint32_t*)(q1p + kk + 2 * cq);
            a[2] = *(const uint32_t*)(q0p + kk + 8 + 2 * cq);
            a[3] = *(const uint32_t*)(q1p + kk + 8 + 2 * cq);
#pragma unroll
            for (int ni = 0; ni < 8; ni++) {
                int key = ni * 8 + (lane >> 2);
                uint32_t bb[2];
                bb[0] = *(const uint32_t*)(ks + key * QSH + kk + 2 * cq);
                bb[1] = *(const uint32_t*)(ks + key * QSH + kk + 8 + 2 * cq);
                mma_f16(sacc[ni], a, bb);
            }
        }

        // causal mask (diagonal tile only)
        if (kt == qt) {
            int kb = kt * AK + 2 * cq;
#pragma unroll
            for (int ni = 0; ni < 8; ni++) {
                int kc = kb + ni * 8;
                if (kc     > q0) sacc[ni][0] = -INFINITY;
                if (kc + 1 > q0) sacc[ni][1] = -INFINITY;
                if (kc     > q1) sacc[ni][2] = -INFINITY;
                if (kc + 1 > q1) sacc[ni][3] = -INFINITY;
            }
        }

        // online softmax
        float t0 = -INFINITY, t1 = -INFINITY;
#pragma unroll
        for (int ni = 0; ni < 8; ni++) {
            t0 = fmaxf(t0, fmaxf(sacc[ni][0], sacc[ni][1]));
            t1 = fmaxf(t1, fmaxf(sacc[ni][2], sacc[ni][3]));
        }
        t0 = fmaxf(t0, __shfl_xor_sync(0xffffffffu, t0, 1));
        t0 = fmaxf(t0, __shfl_xor_sync(0xffffffffu, t0, 2));
        t1 = fmaxf(t1, __shfl_xor_sync(0xffffffffu, t1, 1));
        t1 = fmaxf(t1, __shfl_xor_sync(0xffffffffu, t1, 2));

        float n0 = fmaxf(m0, t0), n1 = fmaxf(m1, t1);
        float c0 = __expf(m0 - n0), c1 = __expf(m1 - n1);
        float s0 = 0.f, s1 = 0.f;
#pragma unroll
        for (int ni = 0; ni < 8; ni++) {
            sacc[ni][0] = __expf(sacc[ni][0] - n0);
            sacc[ni][1] = __expf(sacc[ni][1] - n0);
            sacc[ni][2] = __expf(sacc[ni][2] - n1);
            sacc[ni][3] = __expf(sacc[ni][3] - n1);
            s0 += sacc[ni][0] + sacc[ni][1];
            s1 += sacc[ni][2] + sacc[ni][3];
        }
        s0 += __shfl_xor_sync(0xffffffffu, s0, 1);
        s0 += __shfl_xor_sync(0xffffffffu, s0, 2);
        s1 += __shfl_xor_sync(0xffffffffu, s1, 1);
        s1 += __shfl_xor_sync(0xffffffffu, s1, 2);
        l0 = l0 * c0 + s0;  l1 = l1 * c1 + s1;
        m0 = n0;            m1 = n1;

#pragma unroll
        for (int ni = 0; ni < 16; ni++) {
            oacc[ni][0] *= c0; oacc[ni][1] *= c0;
            oacc[ni][2] *= c1; oacc[ni][3] *= c1;
        }

        // O += P @ Vtile : 4 k16 steps, P packed from registers
#pragma unroll
        for (int s = 0; s < 4; s++) {
            uint32_t a[4];
            a[0] = packh2(sacc[2 * s][0],     sacc[2 * s][1]);
            a[1] = packh2(sacc[2 * s][2],     sacc[2 * s][3]);
            a[2] = packh2(sacc[2 * s + 1][0], sacc[2 * s + 1][1]);
            a[3] = packh2(sacc[2 * s + 1][2], sacc[2 * s + 1][3]);
#pragma unroll
            for (int ni = 0; ni < 16; ni++) {
                int d = ni * 8 + (lane >> 2);
                uint32_t bb[2];
                bb[0] = *(const uint32_t*)(vs + d * VSH + 16 * s + 2 * cq);
                bb[1] = *(const uint32_t*)(vs + d * VSH + 16 * s + 8 + 2 * cq);
                mma_f16(oacc[ni], a, bb);
            }
        }
    }

    // Epilogue: O-proj A-fragment layout. mt = global 16-row tile index.
    float i0 = 1.f / l0, i1 = 1.f / l1;
    const int mt = b * 128 + qt * 4 + w;
#pragma unroll
    for (int ni = 0; ni < 16; ni++) {
        int ktile = h * 8 + (ni >> 1);
        int j = (ni & 1) ? 2 : 0;
        size_t idx = (((size_t)mt * ((NH * DH) / 16) + ktile) * 32 + lane) * 4;
        Op4[idx + j]     = packh2(oacc[ni][0] * i0, oacc[ni][1] * i0);
        Op4[idx + j + 1] = packh2(oacc[ni][2] * i1, oacc[ni][3] * i1);
    }
}

// ---------------------------------------------------------------------------
// Launch
// ---------------------------------------------------------------------------
extern "C" void kernel_launch(void* const* d_in, const int* in_sizes, int n_in,
                              void* d_out, int out_size)
{
    const float* x     = (const float*)d_in[0];
    const float* freqs = (const float*)d_in[1];
    const float* wq    = (const float*)d_in[2];
    const float* wk    = (const float*)d_in[3];
    const float* wv    = (const float*)d_in[4];
    const float* wo    = (const float*)d_in[5];
    float* out = (float*)d_out;

    __half *Qh, *Kh, *Vt;
    uint32_t *xp4, *Op4, *wqkv2, *wop2;
    cudaGetSymbolAddress((void**)&Qh,  g_Qh);
    cudaGetSymbolAddress((void**)&Kh,  g_Kh);
    cudaGetSymbolAddress((void**)&Vt,  g_Vt);
    cudaGetSymbolAddress((void**)&xp4, g_xp4);
    cudaGetSymbolAddress((void**)&Op4, g_Op4);
    cudaGetSymbolAddress((void**)&wqkv2, g_wqkv2);
    cudaGetSymbolAddress((void**)&wop2, g_wop2);

    // Mega-prep
    prep_all<<<(NU_TOTAL + 255) / 256, 256>>>(x, wq, wk, wv, wo,
                                              xp4, wqkv2, wop2);

    cudaFuncSetAttribute(gemm_qkv, cudaFuncAttributeMaxDynamicSharedMemorySize, HSMEM);
    cudaFuncSetAttribute(gemm_o,   cudaFuncAttributeMaxDynamicSharedMemorySize, HSMEM);

    // Fused QKV projection
    {
        dim3 g(NQKV / 256, ROWS / 128);            // (12, 32)
        gemm_qkv<<<g, 256, HSMEM>>>(xp4, wqkv2, Qh, Kh, Vt);
    }

    // RoPE
    {
        int total = ROWS * NH * (DH / 2) + ROWS * NKV * (DH / 2);
        rope_h<<<(total + 255) / 256, 256>>>(Qh, Kh, freqs);
    }

    // Attention -> g_Op4 (AQ=64, 2 CTAs/SM)
    {
        cudaFuncSetAttribute(attn_h, cudaFuncAttributeMaxDynamicSharedMemorySize, ATT_SMEM);
        dim3 ga(S_LEN / AQ, B_SZ * NH);            // (32, 32) = 1024 blocks
        attn_h<<<ga, 128, ATT_SMEM>>>(Qh, Kh, Vt, Op4);
    }

    // Output projection
    {
        dim3 go(HID / 256, ROWS / 128);            // (8, 32)
        gemm_o<<<go, 256, HSMEM>>>(Op4, wop2, out, ROWS, HID, NH * DH);
    }
}

// round 17
// speedup vs baseline: 1.0205x; 1.0205x over previous
#include <cuda_runtime.h>
#include <cuda_fp16.h>
#include <math.h>
#include <stdint.h>

// Problem constants
#define B_SZ   2
#define S_LEN  2048
#define HID    2048
#define NH     16
#define NKV    4
#define DH     128
#define GROUPS (NH / NKV)
#define ROWS   (B_SZ * S_LEN)        // 4096
#define NQKV   (NH * DH + 2 * NKV * DH)   // 3072

// Scratch
__device__ __half   g_Qh[ROWS * NH * DH];
__device__ __half   g_Kh[ROWS * NKV * DH];
__device__ __half   g_Vt[B_SZ * NKV * DH * S_LEN];   // [b][kvh][d][s]
__device__ uint32_t g_xp4[(ROWS / 16) * (HID / 16) * 32 * 4];
__device__ uint32_t g_Op4[(ROWS / 16) * ((NH * DH) / 16) * 32 * 4];
__device__ uint32_t g_wqkv2[(NQKV / 8) * (HID / 16) * 32 * 2];       // Q|K|V B-frags
__device__ uint32_t g_wop2[(HID / 8) * ((NH * DH) / 16) * 32 * 2];

// ---------------------------------------------------------------------------
// Helpers
// ---------------------------------------------------------------------------
__device__ __forceinline__ void mma_f16(float* d, const uint32_t* a, const uint32_t* b) {
    asm volatile(
        "mma.sync.aligned.m16n8k16.row.col.f32.f16.f16.f32 "
        "{%0,%1,%2,%3}, {%4,%5,%6,%7}, {%8,%9}, {%0,%1,%2,%3};\n"
        : "+f"(d[0]), "+f"(d[1]), "+f"(d[2]), "+f"(d[3])
        : "r"(a[0]), "r"(a[1]), "r"(a[2]), "r"(a[3]),
          "r"(b[0]), "r"(b[1]));
}

__device__ __forceinline__ uint32_t packh2(float a, float b) {
    __half2 h = __floats2half2_rn(a, b);
    return *(uint32_t*)&h;
}

__device__ __forceinline__ uint32_t smem_u32(const void* p) {
    return (uint32_t)__cvta_generic_to_shared(p);
}

#define CP16(dst, src) asm volatile("cp.async.cg.shared.global [%0], [%1], 16;" :: "r"(dst), "l"(src))
#define CP_COMMIT()    asm volatile("cp.async.commit_group;")
#define CP_WAIT(n)     asm volatile("cp.async.wait_group %0;" :: "n"(n))

// ---------------------------------------------------------------------------
// Mega-prep: all 5 permutes in one launch.
// ---------------------------------------------------------------------------
#define NU_A   ((ROWS / 16) * (HID / 16) * 32)
#define NU_WQ  (((NH * DH) / 8) * (HID / 16) * 32)
#define NU_WKV (((NKV * DH) / 8) * (HID / 16) * 32)
#define NU_WO  ((HID / 8) * ((NH * DH) / 16) * 32)
#define NU_TOTAL (NU_A + NU_WQ + 2 * NU_WKV + NU_WO)

__device__ __forceinline__ void permA_unit(
    const float* __restrict__ in, uint32_t* __restrict__ out, int K, int id)
{
    int KT = K >> 4;
    int lane = id & 31;
    int kt   = (id >> 5) % KT;
    int mt   = (id >> 5) / KT;
    int r  = mt * 16 + (lane >> 2);
    int cb = kt * 16 + 2 * (lane & 3);
    const float* p0 = in + (size_t)r * K + cb;
    const float* p1 = p0 + (size_t)8 * K;
    uint4 v;
    v.x = packh2(p0[0], p0[1]);
    v.y = packh2(p1[0], p1[1]);
    v.z = packh2(p0[8], p0[9]);
    v.w = packh2(p1[8], p1[9]);
    ((uint4*)out)[id] = v;
}

__device__ __forceinline__ void permB_unit(
    const float* __restrict__ in, uint32_t* __restrict__ out, int K, int N, int id)
{
    int KT = K >> 4;
    int lane = id & 31;
    int kt   = (id >> 5) % KT;
    int nt   = (id >> 5) / KT;
    int n  = nt * 8 + (lane >> 2);
    int kb = kt * 16 + 2 * (lane & 3);
    uint2 v;
    v.x = packh2(in[(size_t)kb * N + n],       in[(size_t)(kb + 1) * N + n]);
    v.y = packh2(in[(size_t)(kb + 8) * N + n], in[(size_t)(kb + 9) * N + n]);
    ((uint2*)out)[id] = v;
}

__global__ __launch_bounds__(256) void prep_all(
    const float* __restrict__ x,  const float* __restrict__ wq,
    const float* __restrict__ wk, const float* __restrict__ wv,
    const float* __restrict__ wo,
    uint32_t* __restrict__ xp4, uint32_t* __restrict__ wqkv2,
    uint32_t* __restrict__ wop2)
{
    int id = blockIdx.x * 256 + threadIdx.x;
    if (id < NU_A) {
        permA_unit(x, xp4, HID, id);
    } else if (id < NU_A + NU_WQ) {
        permB_unit(wq, wqkv2, HID, NH * DH, id - NU_A);
    } else if (id < NU_A + NU_WQ + NU_WKV) {
        permB_unit(wk, wqkv2 + (size_t)NU_WQ * 2, HID, NKV * DH,
                   id - NU_A - NU_WQ);
    } else if (id < NU_A + NU_WQ + 2 * NU_WKV) {
        permB_unit(wv, wqkv2 + (size_t)(NU_WQ + NU_WKV) * 2, HID, NKV * DH,
                   id - NU_A - NU_WQ - NU_WKV);
    } else if (id < NU_TOTAL) {
        permB_unit(wo, wop2, NH * DH, HID, id - NU_A - NU_WQ - 2 * NU_WKV);
    }
}

// ---------------------------------------------------------------------------
// Shared GEMM config (128x256 tile, 8 warps, BK=64, 4 stages).
// ---------------------------------------------------------------------------
#define HSA 16384
#define HSB 32768
#define HSTG (HSA + HSB)
#define HNSTG 4
#define HSMEM (HNSTG * HSTG)      // 196,608

__global__ __launch_bounds__(256, 1) void gemm_qkv(
    const uint32_t* __restrict__ Ap, const uint32_t* __restrict__ Bp,
    __half* __restrict__ Qh, __half* __restrict__ Kh, __half* __restrict__ Vt)
{
    extern __shared__ __align__(16) char smem[];

    const int tid  = threadIdx.x;
    const int lane = tid & 31;
    const int w    = tid >> 5;
    const int wm   = (w >> 2) * 64;
    const int wn   = (w & 3) * 64;
    const int bm   = blockIdx.y * 128;
    const int bn   = blockIdx.x * 256;

    const int K    = HID;
    const int KT16 = K >> 4;
    const int NT   = K >> 6;
    const int mt0  = bm >> 4;
    const int nt0  = bn >> 3;

    auto fill = [&](int buf, int kt0) {
        char* sA = smem + buf * HSTG;
        char* sB = sA + HSA;
#pragma unroll
        for (int i = 0; i < 4; i++) {
            int id = i * 256 + tid;
            int mt_i = id >> 7, kt_i = (id >> 5) & 3, ln = id & 31;
            size_t g = (((size_t)(mt0 + mt_i) * KT16 + kt0 + kt_i) * 32 + ln);
            CP16(smem_u32(sA + id * 16), (const char*)Ap + g * 16);
        }
#pragma unroll
        for (int i = 0; i < 8; i++) {
            int id = i * 256 + tid;
            int nt_i = id >> 6, kt_i = (id >> 4) & 3, u = id & 15;
            size_t g = (((size_t)(nt0 + nt_i) * KT16 + kt0 + kt_i) * 32 + 2 * u);
            CP16(smem_u32(sB + id * 16), (const char*)Bp + g * 8);
        }
    };

    fill(0, 0); CP_COMMIT();
    fill(1, 4); CP_COMMIT();
    fill(2, 8); CP_COMMIT();

    float acc[4][8][4] = {};

    for (int t = 0; t < NT; t++) {
        CP_WAIT(2);
        __syncthreads();
        if (t + 3 < NT) fill((t + 3) % HNSTG, (t + 3) * 4);
        CP_COMMIT();

        const char* sA = smem + (t % HNSTG) * HSTG;
        const char* sB = sA + HSA;

#pragma unroll
        for (int kt = 0; kt < 4; kt++) {
            uint4 af[4];
            uint2 bf[8];
#pragma unroll
            for (int mi = 0; mi < 4; mi++) {
                int mt_t = (wm >> 4) + mi;
                af[mi] = *(const uint4*)(sA + (((mt_t * 4 + kt) * 32 + lane) << 4));
            }
#pragma unroll
            for (int ni = 0; ni < 8; ni++) {
                int nt_t = (wn >> 3) + ni;
                bf[ni] = *(const uint2*)(sB + (((nt_t * 4 + kt) * 32 + lane) << 3));
            }
#pragma unroll
            for (int mi = 0; mi < 4; mi++)
#pragma unroll
                for (int ni = 0; ni < 8; ni++)
                    mma_f16(acc[mi][ni], (const uint32_t*)&af[mi], (const uint32_t*)&bf[ni]);
        }
    }

    const int region = (bn < NH * DH) ? 0 : (bn < NH * DH + NKV * DH ? 1 : 2);

#pragma unroll
    for (int mi = 0; mi < 4; mi++) {
        int r0 = bm + wm + mi * 16 + (lane >> 2);
#pragma unroll
        for (int ni = 0; ni < 8; ni++) {
            int c = bn + wn + ni * 8 + 2 * (lane & 3);
            float v0 = acc[mi][ni][0], v1 = acc[mi][ni][1];
            float v2 = acc[mi][ni][2], v3 = acc[mi][ni][3];
            if (region == 0) {
                *(uint32_t*)(Qh + (size_t)r0 * (NH * DH) + c)       = packh2(v0, v1);
                *(uint32_t*)(Qh + (size_t)(r0 + 8) * (NH * DH) + c) = packh2(v2, v3);
            } else if (region == 1) {
                int ck = c - NH * DH;
                *(uint32_t*)(Kh + (size_t)r0 * (NKV * DH) + ck)       = packh2(v0, v1);
                *(uint32_t*)(Kh + (size_t)(r0 + 8) * (NKV * DH) + ck) = packh2(v2, v3);
            } else {
                int cc = c - (NH * DH + NKV * DH);
                int b0 = r0 >> 11, s0 = r0 & 2047;
                int kvh = cc >> 7;
                int d0 = cc & 127;
                size_t base0 = (((size_t)(b0 * NKV + kvh) * DH + d0) * S_LEN);
                size_t base1 = base0 + S_LEN;
                Vt[base0 + s0]     = __float2half(v0);
                Vt[base1 + s0]     = __float2half(v1);
                Vt[base0 + s0 + 8] = __float2half(v2);
                Vt[base1 + s0 + 8] = __float2half(v3);
            }
        }
    }
}

__global__ __launch_bounds__(256, 1) void gemm_o(
    const uint32_t* __restrict__ Ap, const uint32_t* __restrict__ Bp,
    float* __restrict__ C, int M, int N, int K)
{
    extern __shared__ __align__(16) char smem[];

    const int tid  = threadIdx.x;
    const int lane = tid & 31;
    const int w    = tid >> 5;
    const int wm   = (w >> 2) * 64;
    const int wn   = (w & 3) * 64;
    const int bm   = blockIdx.y * 128;
    const int bn   = blockIdx.x * 256;

    const int KT16 = K >> 4;
    const int NT   = K >> 6;
    const int mt0  = bm >> 4;
    const int nt0  = bn >> 3;

    auto fill = [&](int buf, int kt0) {
        char* sA = smem + buf * HSTG;
        char* sB = sA + HSA;
#pragma unroll
        for (int i = 0; i < 4; i++) {
            int id = i * 256 + tid;
            int mt_i = id >> 7, kt_i = (id >> 5) & 3, ln = id & 31;
            size_t g = (((size_t)(mt0 + mt_i) * KT16 + kt0 + kt_i) * 32 + ln);
            CP16(smem_u32(sA + id * 16), (const char*)Ap + g * 16);
        }
#pragma unroll
        for (int i = 0; i < 8; i++) {
            int id = i * 256 + tid;
            int nt_i = id >> 6, kt_i = (id >> 4) & 3, u = id & 15;
            size_t g = (((size_t)(nt0 + nt_i) * KT16 + kt0 + kt_i) * 32 + 2 * u);
            CP16(smem_u32(sB + id * 16), (const char*)Bp + g * 8);
        }
    };

    fill(0, 0); CP_COMMIT();
    fill(1, 4); CP_COMMIT();
    fill(2, 8); CP_COMMIT();

    float acc[4][8][4] = {};

    for (int t = 0; t < NT; t++) {
        CP_WAIT(2);
        __syncthreads();
        if (t + 3 < NT) fill((t + 3) % HNSTG, (t + 3) * 4);
        CP_COMMIT();

        const char* sA = smem + (t % HNSTG) * HSTG;
        const char* sB = sA + HSA;

#pragma unroll
        for (int kt = 0; kt < 4; kt++) {
            uint4 af[4];
            uint2 bf[8];
#pragma unroll
            for (int mi = 0; mi < 4; mi++) {
                int mt_t = (wm >> 4) + mi;
                af[mi] = *(const uint4*)(sA + (((mt_t * 4 + kt) * 32 + lane) << 4));
            }
#pragma unroll
            for (int ni = 0; ni < 8; ni++) {
                int nt_t = (wn >> 3) + ni;
                bf[ni] = *(const uint2*)(sB + (((nt_t * 4 + kt) * 32 + lane) << 3));
            }
#pragma unroll
            for (int mi = 0; mi < 4; mi++)
#pragma unroll
                for (int ni = 0; ni < 8; ni++)
                    mma_f16(acc[mi][ni], (const uint32_t*)&af[mi], (const uint32_t*)&bf[ni]);
        }
    }

#pragma unroll
    for (int mi = 0; mi < 4; mi++) {
        int r0 = bm + wm + mi * 16 + (lane >> 2);
#pragma unroll
        for (int ni = 0; ni < 8; ni++) {
            int c = bn + wn + ni * 8 + 2 * (lane & 3);
            *(float2*)(C + (size_t)r0 * N + c) =
                make_float2(acc[mi][ni][0], acc[mi][ni][1]);
            *(float2*)(C + (size_t)(r0 + 8) * N + c) =
                make_float2(acc[mi][ni][2], acc[mi][ni][3]);
        }
    }
}

// ---------------------------------------------------------------------------
// RoPE on half Q/K (fp32 math); Q additionally scaled by 1/sqrt(DH).
// ---------------------------------------------------------------------------
__global__ __launch_bounds__(256) void rope_h(
    __half* __restrict__ Q, __half* __restrict__ Kt,
    const float* __restrict__ freqs)
{
    const int QP = ROWS * NH * (DH / 2);
    const int KP = ROWS * NKV * (DH / 2);
    const float scale = 0.08838834764831845f;
    int idx = blockIdx.x * blockDim.x + threadIdx.x;
    if (idx < QP) {
        int i   = idx & 63;
        int h   = (idx >> 6) & (NH - 1);
        int row = idx >> 10;
        int s   = row & (S_LEN - 1);
        float c  = freqs[s * 128 + 2 * i];
        float sn = freqs[s * 128 + 2 * i + 1];
        __half2* p = (__half2*)(Q + (size_t)row * (NH * DH) + h * DH + 2 * i);
        float2 v = __half22float2(*p);
        *p = __floats2half2_rn((v.x * c - v.y * sn) * scale,
                               (v.x * sn + v.y * c) * scale);
    } else if (idx < QP + KP) {
        int j   = idx - QP;
        int i   = j & 63;
        int h   = (j >> 6) & (NKV - 1);
        int row = j >> 8;
        int s   = row & (S_LEN - 1);
        float c  = freqs[s * 128 + 2 * i];
        float sn = freqs[s * 128 + 2 * i + 1];
        __half2* p = (__half2*)(Kt + (size_t)row * (NKV * DH) + h * DH + 2 * i);
        float2 v = __half22float2(*p);
        *p = __floats2half2_rn(v.x * c - v.y * sn, v.x * sn + v.y * c);
    }
}

// ---------------------------------------------------------------------------
// FP16 flash attention (causal, GQA). AQ=64, AK=64, 128 threads (4 warps),
// 2 CTAs/SM. Warp-uniform skip of oacc rescale when max unchanged.
// ---------------------------------------------------------------------------
#define AQ 64
#define AK 64
#define QSH 136
#define VSH 72
#define ATT_SMEM ((AQ * QSH + 2 * AK * QSH + 2 * DH * VSH) * 2)

__global__ __launch_bounds__(128) void attn_h(
    const __half* __restrict__ Q, const __half* __restrict__ K,
    const __half* __restrict__ Vt, uint32_t* __restrict__ Op4)
{
    extern __shared__ __align__(16) __half sh[];
    __half* Qs  = sh;                        // [64][136]
    __half* Ks  = Qs + AQ * QSH;             // 2 x [64][136]
    __half* Vts = Ks + 2 * AK * QSH;         // 2 x [128][72]

    const int qt  = gridDim.x - 1 - blockIdx.x;   // heavy blocks first
    const int bh  = blockIdx.y;
    const int b   = bh >> 4;
    const int h   = bh & 15;
    const int kvh = h >> 2;
    const int tid = threadIdx.x;
    const int lane = tid & 31;
    const int w    = tid >> 5;               // 0..3
    const int cq   = lane & 3;

    const size_t qbaseH = ((size_t)(b * S_LEN + qt * AQ)) * (NH * DH) + h * DH;
#pragma unroll
    for (int i = 0; i < 8; i++) {
        int t = i * 128 + tid;
        int r = t >> 4, u = t & 15;
        CP16(smem_u32(Qs + r * QSH + u * 8), Q + qbaseH + (size_t)r * (NH * DH) + u * 8);
    }

    const size_t kbaseH  = ((size_t)(b * S_LEN)) * (NKV * DH) + kvh * DH;
    const size_t vtbaseH = ((size_t)(b * NKV + kvh)) * DH * S_LEN;

    auto issueKV = [&](int buf, int kt) {
        __half* ks = Ks + buf * AK * QSH;
        __half* vs = Vts + buf * DH * VSH;
#pragma unroll
        for (int i = 0; i < 8; i++) {
            int id = i * 128 + tid;
            int r = id >> 4, u = id & 15;
            CP16(smem_u32(ks + r * QSH + u * 8),
                 K + kbaseH + (size_t)(kt * AK + r) * (NKV * DH) + u * 8);
        }
#pragma unroll
        for (int i = 0; i < 8; i++) {
            int id = i * 128 + tid;
            int d = id >> 3, u = id & 7;
            CP16(smem_u32(vs + d * VSH + u * 8),
                 Vt + vtbaseH + (size_t)d * S_LEN + kt * AK + u * 8);
        }
    };

    const int KT = qt + 1;
    issueKV(0, 0); CP_COMMIT();

    const int rA = w * 16 + (lane >> 2);
    const int q0 = qt * AQ + rA;
    const int q1 = q0 + 8;

    float m0 = -INFINITY, m1 = -INFINITY, l0 = 0.f, l1 = 0.f;
    float oacc[16][4] = {};

    for (int kt = 0; kt < KT; kt++) {
        __syncthreads();
        if (kt + 1 < KT) issueKV((kt + 1) & 1, kt + 1);
        CP_COMMIT();
        CP_WAIT(1);
        __syncthreads();

        const __half* ks = Ks + (kt & 1) * AK * QSH;
        const __half* vs = Vts + (kt & 1) * DH * VSH;

        // S = Q @ Ktile^T
        float sacc[8][4] = {};
        const __half* q0p = Qs + rA * QSH;
        const __half* q1p = q0p + 8 * QSH;
#pragma unroll
        for (int kk = 0; kk < DH; kk += 16) {
            uint32_t a[4];
            a[0] = *(const uint32_t*)(q0p + kk + 2 * cq);
            a[1] = *(const uint32_t*)(q1p + kk + 2 * cq);
            a[2] = *(const uint32_t*)(q0p + kk + 8 + 2 * cq);
            a[3] = *(const uint32_t*)(q1p + kk + 8 + 2 * cq);
#pragma unroll
            for (int ni = 0; ni < 8; ni++) {
                int key = ni * 8 + (lane >> 2);
                uint32_t bb[2];
                bb[0] = *(const uint32_t*)(ks + key * QSH + kk + 2 * cq);
                bb[1] = *(const uint32_t*)(ks + key * QSH + kk + 8 + 2 * cq);
                mma_f16(sacc[ni], a, bb);
            }
        }

        // causal mask (diagonal tile only)
        if (kt == qt) {
            int kb = kt * AK + 2 * cq;
#pragma unroll
            for (int ni = 0; ni < 8; ni++) {
                int kc = kb + ni * 8;
                if (kc     > q0) sacc[ni][0] = -INFINITY;
                if (kc + 1 > q0) sacc[ni][1] = -INFINITY;
                if (kc     > q1) sacc[ni][2] = -INFINITY;
                if (kc + 1 > q1) sacc[ni][3] = -INFINITY;
            }
        }

        // online softmax (warp-uniform rescale skip)
        float t0 = -INFINITY, t1 = -INFINITY;
#pragma unroll
        for (int ni = 0; ni < 8; ni++) {
            t0 = fmaxf(t0, fmaxf(sacc[ni][0], sacc[ni][1]));
            t1 = fmaxf(t1, fmaxf(sacc[ni][2], sacc[ni][3]));
        }
        t0 = fmaxf(t0, __shfl_xor_sync(0xffffffffu, t0, 1));
        t0 = fmaxf(t0, __shfl_xor_sync(0xffffffffu, t0, 2));
        t1 = fmaxf(t1, __shfl_xor_sync(0xffffffffu, t1, 1));
        t1 = fmaxf(t1, __shfl_xor_sync(0xffffffffu, t1, 2));

        float n0 = fmaxf(m0, t0), n1 = fmaxf(m1, t1);
        unsigned upd = __ballot_sync(0xffffffffu, (n0 > m0) || (n1 > m1));

        float s0 = 0.f, s1 = 0.f;
#pragma unroll
        for (int ni = 0; ni < 8; ni++) {
            sacc[ni][0] = __expf(sacc[ni][0] - n0);
            sacc[ni][1] = __expf(sacc[ni][1] - n0);
            sacc[ni][2] = __expf(sacc[ni][2] - n1);
            sacc[ni][3] = __expf(sacc[ni][3] - n1);
            s0 += sacc[ni][0] + sacc[ni][1];
            s1 += sacc[ni][2] + sacc[ni][3];
        }
        s0 += __shfl_xor_sync(0xffffffffu, s0, 1);
        s0 += __shfl_xor_sync(0xffffffffu, s0, 2);
        s1 += __shfl_xor_sync(0xffffffffu, s1, 1);
        s1 += __shfl_xor_sync(0xffffffffu, s1, 2);

        if (upd) {
            float c0 = __expf(m0 - n0), c1 = __expf(m1 - n1);
            l0 = l0 * c0 + s0;  l1 = l1 * c1 + s1;
#pragma unroll
            for (int ni = 0; ni < 16; ni++) {
                oacc[ni][0] *= c0; oacc[ni][1] *= c0;
                oacc[ni][2] *= c1; oacc[ni][3] *= c1;
            }
        } else {
            l0 += s0;  l1 += s1;   // corr == 1 exactly
        }
        m0 = n0;  m1 = n1;

        // O += P @ Vtile : 4 k16 steps, P packed from registers
#pragma unroll
        for (int s = 0; s < 4; s++) {
            uint32_t a[4];
            a[0] = packh2(sacc[2 * s][0],     sacc[2 * s][1]);
            a[1] = packh2(sacc[2 * s][2],     sacc[2 * s][3]);
            a[2] = packh2(sacc[2 * s + 1][0], sacc[2 * s + 1][1]);
            a[3] = packh2(sacc[2 * s + 1][2], sacc[2 * s + 1][3]);
#pragma unroll
            for (int ni = 0; ni < 16; ni++) {
                int d = ni * 8 + (lane >> 2);
                uint32_t bb[2];
                bb[0] = *(const uint32_t*)(vs + d * VSH + 16 * s + 2 * cq);
                bb[1] = *(const uint32_t*)(vs + d * VSH + 16 * s + 8 + 2 * cq);
                mma_f16(oacc[ni], a, bb);
            }
        }
    }

    // Epilogue: O-proj A-fragment layout.
    float i0 = 1.f / l0, i1 = 1.f / l1;
    const int mt = b * 128 + qt * 4 + w;
#pragma unroll
    for (int ni = 0; ni < 16; ni++) {
        int ktile = h * 8 + (ni >> 1);
        int j = (ni & 1) ? 2 : 0;
        size_t idx = (((size_t)mt * ((NH * DH) / 16) + ktile) * 32 + lane) * 4;
        Op4[idx + j]     = packh2(oacc[ni][0] * i0, oacc[ni][1] * i0);
        Op4[idx + j + 1] = packh2(oacc[ni][2] * i1, oacc[ni][3] * i1);
    }
}

// ---------------------------------------------------------------------------
// Launch
// ---------------------------------------------------------------------------
extern "C" void kernel_launch(void* const* d_in, const int* in_sizes, int n_in,
                              void* d_out, int out_size)
{
    const float* x     = (const float*)d_in[0];
    const float* freqs = (const float*)d_in[1];
    const float* wq    = (const float*)d_in[2];
    const float* wk    = (const float*)d_in[3];
    const float* wv    = (const float*)d_in[4];
    const float* wo    = (const float*)d_in[5];
    float* out = (float*)d_out;

    __half *Qh, *Kh, *Vt;
    uint32_t *xp4, *Op4, *wqkv2, *wop2;
    cudaGetSymbolAddress((void**)&Qh,  g_Qh);
    cudaGetSymbolAddress((void**)&Kh,  g_Kh);
    cudaGetSymbolAddress((void**)&Vt,  g_Vt);
    cudaGetSymbolAddress((void**)&xp4, g_xp4);
    cudaGetSymbolAddress((void**)&Op4, g_Op4);
    cudaGetSymbolAddress((void**)&wqkv2, g_wqkv2);
    cudaGetSymbolAddress((void**)&wop2, g_wop2);

    // Mega-prep
    prep_all<<<(NU_TOTAL + 255) / 256, 256>>>(x, wq, wk, wv, wo,
                                              xp4, wqkv2, wop2);

    cudaFuncSetAttribute(gemm_qkv, cudaFuncAttributeMaxDynamicSharedMemorySize, HSMEM);
    cudaFuncSetAttribute(gemm_o,   cudaFuncAttributeMaxDynamicSharedMemorySize, HSMEM);

    // Fused QKV projection
    {
        dim3 g(NQKV / 256, ROWS / 128);            // (12, 32)
        gemm_qkv<<<g, 256, HSMEM>>>(xp4, wqkv2, Qh, Kh, Vt);
    }

    // RoPE
    {
        int total = ROWS * NH * (DH / 2) + ROWS * NKV * (DH / 2);
        rope_h<<<(total + 255) / 256, 256>>>(Qh, Kh, freqs);
    }

    // Attention -> g_Op4
    {
        cudaFuncSetAttribute(attn_h, cudaFuncAttributeMaxDynamicSharedMemorySize, ATT_SMEM);
        dim3 ga(S_LEN / AQ, B_SZ * NH);            // (32, 32) = 1024 blocks
        attn_h<<<ga, 128, ATT_SMEM>>>(Qh, Kh, Vt, Op4);
    }

    // Output projection
    {
        dim3 go(HID / 256, ROWS / 128);            // (8, 32)
        gemm_o<<<go, 256, HSMEM>>>(Op4, wop2, out, ROWS, HID, NH * DH);
    }
}